// round 4
// baseline (speedup 1.0000x reference)
#include <cuda_runtime.h>

// QuantumConvolution: B=32, Cin=8, Cout=16, H=W=32, K=3, NQ=3, DRC=3, IT=30.
// R4: R3 (packed fma.rn.f32x2, layer-0 sparsity, cin-per-lane) + occupancy fix:
//     pos-loop unroll 1, launch_bounds(256,2) -> <=128 regs -> 2 blocks/SM,
//     per-layer window/param loads to shorten live ranges.

#define BB    32
#define CIN   8
#define COUT  16
#define HW    32
#define ITDIM 30
#define NPOS  (ITDIM * ITDIM)   // 900
#define NTHREADS 256
#define CH_STRIDE 1060          // per-channel smem floats: cin lanes hit distinct banks
#define RP_STRIDE 39            // ulonglong2 per cin

typedef unsigned long long ull;

__device__ __forceinline__ ull pk2(float lo, float hi) {
    ull r; asm("mov.b64 %0, {%1, %2};" : "=l"(r) : "f"(lo), "f"(hi)); return r;
}
__device__ __forceinline__ ull bc2(float v) { return pk2(v, v); }
__device__ __forceinline__ ull swap2(ull a) {
    ull r;
    asm("{\n\t.reg .b32 lo, hi;\n\tmov.b64 {lo, hi}, %1;\n\tmov.b64 %0, {hi, lo};\n\t}"
        : "=l"(r) : "l"(a));
    return r;
}
__device__ __forceinline__ ull fma2(ull a, ull b, ull c) {
    ull d; asm("fma.rn.f32x2 %0, %1, %2, %3;" : "=l"(d) : "l"(a), "l"(b), "l"(c)); return d;
}
__device__ __forceinline__ ull mul2(ull a, ull b) {
    ull d; asm("mul.rn.f32x2 %0, %1, %2;" : "=l"(d) : "l"(a), "l"(b)); return d;
}
__device__ __forceinline__ void upk2(ull a, float& lo, float& hi) {
    asm("mov.b64 {%0, %1}, %2;" : "=f"(lo), "=f"(hi) : "l"(a));
}
__device__ __forceinline__ ull mkpk(float lo, float hi) {
    return (ull)__float_as_uint(lo) | ((ull)__float_as_uint(hi) << 32);
}

__global__ __launch_bounds__(NTHREADS, 2)
void qconv_kernel(const float* __restrict__ inputs,        // [32][8][32][32]
                  const float* __restrict__ input_params,  // [16][8][3][3]
                  const float* __restrict__ weights,       // [16][8][3][3][3]
                  float* __restrict__ out)                 // [32][16][30][30]
{
    __shared__ float      s_in[CIN * CH_STRIDE];
    __shared__ float      s_pm[CIN][9];              // 0.5 * input_params
    __shared__ ulonglong2 s_rp[CIN][RP_STRIDE];      // packed Rot constants

    const int cout = blockIdx.x;
    const int b    = blockIdx.y;
    const int tid  = threadIdx.x;
    const int cin  = tid & 7;        // lane's input channel
    const int grp  = tid >> 3;       // 32 position groups

    // ---- Load input patch (float4, coalesced) into padded smem ----
    const float4* inb4 = (const float4*)(inputs + (size_t)b * (CIN * HW * HW));
    #pragma unroll
    for (int k = 0; k < 8; k++) {
        int idx = k * NTHREADS + tid;        // 2048 float4 total
        int c   = idx >> 8;
        int rem = idx & 255;
        int row = rem >> 3;
        int col = (rem & 7) * 4;
        float4 v = inb4[idx];
        float* dst = &s_in[c * CH_STRIDE + row * 33 + col];
        dst[0] = v.x; dst[1] = v.y; dst[2] = v.z; dst[3] = v.w;
    }

    // ---- Precompute packed Rot constants + half params ----
    if (tid < CIN * 9) {
        int pc = tid / 9;
        int g  = tid % 9;
        s_pm[pc][g] = 0.5f * input_params[(cout * CIN + pc) * 9 + g];

        const float* w = weights + (((size_t)cout * CIN + pc) * 9 + g) * 3;
        float phi = w[0], th = w[1], om = w[2];
        float st, ct;  sincosf(0.5f * th, &st, &ct);
        float sa, ca;  sincosf(0.5f * (phi + om), &sa, &ca);
        float sb, cb;  sincosf(0.5f * (phi - om), &sb, &cb);
        float u00r =  ca * ct, u00i = -sa * ct;
        float u01r = -cb * st, u01i = -sb * st;
        float u10r =  cb * st, u10i = -sb * st;
        float u11r =  ca * ct, u11i =  sa * ct;
        ulonglong2 e;
        e.x = mkpk(u00r, u00r); e.y = mkpk(-u00i, u00i); s_rp[pc][g * 4 + 0] = e;
        e.x = mkpk(u01r, u01r); e.y = mkpk(-u01i, u01i); s_rp[pc][g * 4 + 1] = e;
        e.x = mkpk(u10r, u10r); e.y = mkpk(-u10i, u10i); s_rp[pc][g * 4 + 2] = e;
        e.x = mkpk(u11r, u11r); e.y = mkpk(-u11i, u11i); s_rp[pc][g * 4 + 3] = e;
        if (g == 0) {  // real-input packs for layer-0 qubit-0 Rot
            e.x = mkpk(u00r, u00i); e.y = mkpk(u01r, u01i); s_rp[pc][36] = e;
            e.x = mkpk(u10r, u10i); e.y = mkpk(u11r, u11i); s_rp[pc][37] = e;
        }
    }
    __syncthreads();

    const float* chan = &s_in[cin * CH_STRIDE];
    const float* pmc  = s_pm[cin];

    #pragma unroll 1
    for (int pos = grp; pos < NPOS; pos += 32) {
        const int i = pos / ITDIM;
        const int j = pos % ITDIM;
        const float* win = chan + i * 33 + j;

        ull s[8];

        // ======== Layer 0 (sparse |000> fast path) ========
        {
            float sn0, cs0, sn1, cs1, sn2c, cs2c;
            __sincosf(win[0] * pmc[0], &sn0, &cs0);
            __sincosf(win[1] * pmc[1], &sn1, &cs1);
            __sincosf(win[2] * pmc[2], &sn2c, &cs2c);
            float t0 = cs0 * cs1, t1 = cs0 * sn1, t2 = sn0 * cs1, t3 = sn0 * sn1;
            float r0 = t0 * cs2c, r1 = t0 * sn2c, r2 = t1 * cs2c, r3 = t1 * sn2c;
            float r4 = t2 * cs2c, r5 = t2 * sn2c, r6 = t3 * cs2c, r7 = t3 * sn2c;

            // Rot on qubit 0 (stride 4), real inputs
            ulonglong2 ra = s_rp[cin][36];   // {pk(u00), pk(u01)}
            ulonglong2 rb = s_rp[cin][37];   // {pk(u10), pk(u11)}
            s[0] = fma2(ra.y, bc2(r4), mul2(ra.x, bc2(r0)));
            s[4] = fma2(rb.y, bc2(r4), mul2(rb.x, bc2(r0)));
            s[1] = fma2(ra.y, bc2(r5), mul2(ra.x, bc2(r1)));
            s[5] = fma2(rb.y, bc2(r5), mul2(rb.x, bc2(r1)));
            s[2] = fma2(ra.y, bc2(r6), mul2(ra.x, bc2(r2)));
            s[6] = fma2(rb.y, bc2(r6), mul2(rb.x, bc2(r2)));
            s[3] = fma2(ra.y, bc2(r7), mul2(ra.x, bc2(r3)));
            s[7] = fma2(rb.y, bc2(r7), mul2(rb.x, bc2(r3)));
        }

        // General complex Rot gate on pair stride ST
        #define ROT_GATE(G, ST)                                                     \
        {                                                                           \
            ulonglong2 c0 = s_rp[cin][(G) * 4 + 0];                                 \
            ulonglong2 c1 = s_rp[cin][(G) * 4 + 1];                                 \
            ulonglong2 c2 = s_rp[cin][(G) * 4 + 2];                                 \
            ulonglong2 c3 = s_rp[cin][(G) * 4 + 3];                                 \
            _Pragma("unroll")                                                       \
            for (int a = 0; a < 8; a++) {                                           \
                if ((a & (ST)) == 0) {                                              \
                    int p = a | (ST);                                               \
                    ull x0 = s[a], x1 = s[p];                                       \
                    ull x0s = swap2(x0), x1s = swap2(x1);                           \
                    s[a] = fma2(c1.y, x1s, fma2(c1.x, x1,                           \
                             fma2(c0.y, x0s, mul2(c0.x, x0))));                     \
                    s[p] = fma2(c3.y, x1s, fma2(c3.x, x1,                           \
                             fma2(c2.y, x0s, mul2(c2.x, x0))));                     \
                }                                                                   \
            }                                                                       \
        }

        // RY gate: angle = win[row*33+col] * pm[G]
        #define RY_GATE(G, ROW, COL, ST)                                            \
        {                                                                           \
            float sn, cs;                                                           \
            __sincosf(win[(ROW) * 33 + (COL)] * pmc[(G)], &sn, &cs);                \
            ull cs2 = bc2(cs), sn2 = bc2(sn), nsn2 = bc2(-sn);                      \
            _Pragma("unroll")                                                       \
            for (int a = 0; a < 8; a++) {                                           \
                if ((a & (ST)) == 0) {                                              \
                    int p = a | (ST);                                               \
                    ull x0 = s[a], x1 = s[p];                                       \
                    s[a] = fma2(nsn2, x1, mul2(cs2, x0));                           \
                    s[p] = fma2(sn2,  x0, mul2(cs2, x1));                           \
                }                                                                   \
            }                                                                       \
        }

        #define CNOT_RING()                                                         \
        {                                                                           \
            ull t;                                                                  \
            t = s[4]; s[4] = s[6]; s[6] = t;  t = s[5]; s[5] = s[7]; s[7] = t;      \
            t = s[2]; s[2] = s[3]; s[3] = t;  t = s[6]; s[6] = s[7]; s[7] = t;      \
            t = s[1]; s[1] = s[5]; s[5] = t;  t = s[3]; s[3] = s[7]; s[7] = t;      \
        }

        // finish layer 0: Rot on qubits 1, 2, then CNOT ring
        ROT_GATE(1, 2)
        ROT_GATE(2, 1)
        CNOT_RING()

        // ======== Layer 1 ========
        RY_GATE(3, 1, 0, 4)  RY_GATE(4, 1, 1, 2)  RY_GATE(5, 1, 2, 1)
        ROT_GATE(3, 4) ROT_GATE(4, 2) ROT_GATE(5, 1)
        CNOT_RING()

        // ======== Layer 2 ========
        RY_GATE(6, 2, 0, 4)  RY_GATE(7, 2, 1, 2)  RY_GATE(8, 2, 2, 1)
        ROT_GATE(6, 4) ROT_GATE(7, 2) ROT_GATE(8, 1)
        CNOT_RING()

        #undef ROT_GATE
        #undef RY_GATE
        #undef CNOT_RING

        // <Z wire2> = sum_{a even} |amp|^2 - sum_{a odd} |amp|^2
        ull eacc = mul2(s[0], s[0]);
        eacc = fma2(s[2], s[2], eacc);
        eacc = fma2(s[4], s[4], eacc);
        eacc = fma2(s[6], s[6], eacc);
        ull oacc = mul2(s[1], s[1]);
        oacc = fma2(s[3], s[3], oacc);
        oacc = fma2(s[5], s[5], oacc);
        oacc = fma2(s[7], s[7], oacc);
        float er, ei, orr, oi;
        upk2(eacc, er, ei);
        upk2(oacc, orr, oi);
        float acc = (er + ei) - (orr + oi);

        // reduce over the 8 cin lanes
        acc += __shfl_xor_sync(0xFFFFFFFFu, acc, 1);
        acc += __shfl_xor_sync(0xFFFFFFFFu, acc, 2);
        acc += __shfl_xor_sync(0xFFFFFFFFu, acc, 4);
        if (cin == 0)
            out[((size_t)b * COUT + cout) * NPOS + pos] = acc;
    }
}

extern "C" void kernel_launch(void* const* d_in, const int* in_sizes, int n_in,
                              void* d_out, int out_size)
{
    const float* inputs       = (const float*)d_in[0];
    const float* input_params = (const float*)d_in[1];
    const float* weights      = (const float*)d_in[2];
    float* out = (float*)d_out;

    dim3 grid(COUT, BB);   // (cout, b)
    qconv_kernel<<<grid, NTHREADS>>>(inputs, input_params, weights, out);
}

// round 5
// speedup vs baseline: 1.3861x; 1.3861x over previous
#include <cuda_runtime.h>

// QuantumConvolution: B=32, Cin=8, Cout=16, H=W=32, K=3, NQ=3, DRC=3, IT=30.
// R5: scalar FMA (f32x2 shown half-rate -> no benefit), SU(2) gate fusion
//     (Rot*RY built per circuit: 8 FMA build + 64 apply vs 96 unfused),
//     layer-0 |000> sparsity, cin-per-lane + shuffle reduce, natural regs.

#define BB    32
#define CIN   8
#define COUT  16
#define HW    32
#define ITDIM 30
#define NPOS  (ITDIM * ITDIM)   // 900
#define NTHREADS 256
#define CH_STRIDE 1060          // per-channel smem floats: cin lanes on distinct banks

__global__ __launch_bounds__(NTHREADS)
void qconv_kernel(const float* __restrict__ inputs,        // [32][8][32][32]
                  const float* __restrict__ input_params,  // [16][8][3][3]
                  const float* __restrict__ weights,       // [16][8][3][3][3]
                  float* __restrict__ out)                 // [32][16][30][30]
{
    __shared__ float  s_in[CIN * CH_STRIDE];
    __shared__ float  s_pm[CIN][9];       // 0.5 * input_params
    __shared__ float4 s_gc[CIN][9];       // raw Rot row0: (u00r, u00i, u01r, u01i)

    const int cout = blockIdx.x;
    const int b    = blockIdx.y;
    const int tid  = threadIdx.x;
    const int cin  = tid & 7;
    const int grp  = tid >> 3;            // 32 position groups

    // ---- Load input patch (float4, coalesced) into padded smem ----
    const float4* inb4 = (const float4*)(inputs + (size_t)b * (CIN * HW * HW));
    #pragma unroll
    for (int k = 0; k < 8; k++) {
        int idx = k * NTHREADS + tid;      // 2048 float4 total
        int c   = idx >> 8;
        int rem = idx & 255;
        int row = rem >> 3;
        int col = (rem & 7) * 4;
        float4 v = inb4[idx];
        float* dst = &s_in[c * CH_STRIDE + row * 33 + col];
        dst[0] = v.x; dst[1] = v.y; dst[2] = v.z; dst[3] = v.w;
    }

    // ---- Precompute per-(cin,gate): half params + Rot row-0 (SU(2) determines row 1) ----
    if (tid < CIN * 9) {
        int pc = tid / 9;
        int g  = tid % 9;
        s_pm[pc][g] = 0.5f * input_params[(cout * CIN + pc) * 9 + g];

        const float* w = weights + (((size_t)cout * CIN + pc) * 9 + g) * 3;
        float phi = w[0], th = w[1], om = w[2];
        float st, ct;  sincosf(0.5f * th, &st, &ct);
        float sa, ca;  sincosf(0.5f * (phi + om), &sa, &ca);
        float sb, cb;  sincosf(0.5f * (phi - om), &sb, &cb);
        // u00 = ( ca*ct, -sa*ct),  u01 = (-cb*st, -sb*st)
        s_gc[pc][g] = make_float4(ca * ct, -sa * ct, -cb * st, -sb * st);
    }
    __syncthreads();

    const float*  chan = &s_in[cin * CH_STRIDE];
    const float*  pmc  = s_pm[cin];
    const float4* gcc  = s_gc[cin];

    // Apply SU(2) gate V = [[a, -t],[conj(t), conj(a)]] on qubit pairs with stride ST
    #define APPLY(AR, AI, TR, TI, ST)                                           \
    {                                                                           \
        _Pragma("unroll")                                                       \
        for (int a0 = 0; a0 < 8; a0++) {                                        \
            if ((a0 & (ST)) == 0) {                                             \
                int p = a0 | (ST);                                              \
                float x0r = sr[a0], x0i = si[a0];                               \
                float x1r = sr[p],  x1i = si[p];                                \
                sr[a0] = (AR) * x0r - (AI) * x0i - (TR) * x1r + (TI) * x1i;     \
                si[a0] = (AR) * x0i + (AI) * x0r - (TR) * x1i - (TI) * x1r;     \
                sr[p]  = (TR) * x0r + (TI) * x0i + (AR) * x1r + (AI) * x1i;     \
                si[p]  = (TR) * x0i - (TI) * x0r + (AR) * x1i - (AI) * x1r;     \
            }                                                                   \
        }                                                                       \
    }

    // Fused (Rot * RY(theta)) gate: build a = u00*c + u01*s, t = u00*s - u01*c
    #define FUSED_GATE(G, ROW, COL, ST)                                         \
    {                                                                           \
        float sn, cs;                                                           \
        __sincosf(win[(ROW) * 33 + (COL)] * pmc[(G)], &sn, &cs);                \
        float4 u = gcc[(G)];                                                    \
        float ar = u.x * cs + u.z * sn;                                         \
        float ai = u.y * cs + u.w * sn;                                         \
        float tr = u.x * sn - u.z * cs;                                         \
        float ti = u.y * sn - u.w * cs;                                         \
        APPLY(ar, ai, tr, ti, ST)                                               \
    }

    // Pure Rot gate: a = u00, t = -u01
    #define ROT_GATE(G, ST)                                                     \
    {                                                                           \
        float4 u = gcc[(G)];                                                    \
        APPLY(u.x, u.y, -u.z, -u.w, ST)                                         \
    }

    #define CNOT_RING()                                                             \
    {                                                                               \
        float t;                                                                    \
        t = sr[4]; sr[4] = sr[6]; sr[6] = t;  t = si[4]; si[4] = si[6]; si[6] = t;  \
        t = sr[5]; sr[5] = sr[7]; sr[7] = t;  t = si[5]; si[5] = si[7]; si[7] = t;  \
        t = sr[2]; sr[2] = sr[3]; sr[3] = t;  t = si[2]; si[2] = si[3]; si[3] = t;  \
        t = sr[6]; sr[6] = sr[7]; sr[7] = t;  t = si[6]; si[6] = si[7]; si[7] = t;  \
        t = sr[1]; sr[1] = sr[5]; sr[5] = t;  t = si[1]; si[1] = si[5]; si[5] = t;  \
        t = sr[3]; sr[3] = sr[7]; sr[7] = t;  t = si[3]; si[3] = si[7]; si[7] = t;  \
    }

    #pragma unroll 1
    for (int pos = grp; pos < NPOS; pos += 32) {
        const int i = pos / ITDIM;
        const int j = pos % ITDIM;
        const float* win = chan + i * 33 + j;

        float sr[8], si[8];

        // ======== Layer 0: |000> fast path ========
        {
            float sn0, cs0, sn1, cs1, sn2, cs2;
            __sincosf(win[0] * pmc[0], &sn0, &cs0);
            __sincosf(win[1] * pmc[1], &sn1, &cs1);
            __sincosf(win[2] * pmc[2], &sn2, &cs2);
            // real product state after RY x RY x RY
            float t0 = cs0 * cs1, t1 = cs0 * sn1, t2 = sn0 * cs1, t3 = sn0 * sn1;
            float r0 = t0 * cs2, r1 = t0 * sn2, r2 = t1 * cs2, r3 = t1 * sn2;
            float r4 = t2 * cs2, r5 = t2 * sn2, r6 = t3 * cs2, r7 = t3 * sn2;

            // Rot on qubit 0 (stride 4), real inputs.
            // row0 = (u00, u01) = (u.x+i*u.y, u.z+i*u.w); row1 = (-u01*, u00*)
            float4 u = gcc[0];
            sr[0] = u.x * r0 + u.z * r4;   si[0] = u.y * r0 + u.w * r4;
            sr[4] = u.x * r4 - u.z * r0;   si[4] = u.w * r0 - u.y * r4;
            sr[1] = u.x * r1 + u.z * r5;   si[1] = u.y * r1 + u.w * r5;
            sr[5] = u.x * r5 - u.z * r1;   si[5] = u.w * r1 - u.y * r5;
            sr[2] = u.x * r2 + u.z * r6;   si[2] = u.y * r2 + u.w * r6;
            sr[6] = u.x * r6 - u.z * r2;   si[6] = u.w * r2 - u.y * r6;
            sr[3] = u.x * r3 + u.z * r7;   si[3] = u.y * r3 + u.w * r7;
            sr[7] = u.x * r7 - u.z * r3;   si[7] = u.w * r3 - u.y * r7;
        }
        ROT_GATE(1, 2)
        ROT_GATE(2, 1)
        CNOT_RING()

        // ======== Layer 1 (RY fused into Rot) ========
        FUSED_GATE(3, 1, 0, 4)
        FUSED_GATE(4, 1, 1, 2)
        FUSED_GATE(5, 1, 2, 1)
        CNOT_RING()

        // ======== Layer 2 ========
        FUSED_GATE(6, 2, 0, 4)
        FUSED_GATE(7, 2, 1, 2)
        FUSED_GATE(8, 2, 2, 1)
        CNOT_RING()

        // <Z wire2>: + even amp index, - odd
        float acc = 0.f;
        #pragma unroll
        for (int a0 = 0; a0 < 8; a0++) {
            float p2 = sr[a0] * sr[a0] + si[a0] * si[a0];
            acc += (a0 & 1) ? -p2 : p2;
        }

        // reduce over the 8 cin lanes
        acc += __shfl_xor_sync(0xFFFFFFFFu, acc, 1);
        acc += __shfl_xor_sync(0xFFFFFFFFu, acc, 2);
        acc += __shfl_xor_sync(0xFFFFFFFFu, acc, 4);
        if (cin == 0)
            out[((size_t)b * COUT + cout) * NPOS + pos] = acc;
    }

    #undef APPLY
    #undef FUSED_GATE
    #undef ROT_GATE
    #undef CNOT_RING
}

extern "C" void kernel_launch(void* const* d_in, const int* in_sizes, int n_in,
                              void* d_out, int out_size)
{
    const float* inputs       = (const float*)d_in[0];
    const float* input_params = (const float*)d_in[1];
    const float* weights      = (const float*)d_in[2];
    float* out = (float*)d_out;

    dim3 grid(COUT, BB);   // (cout, b)
    qconv_kernel<<<grid, NTHREADS>>>(inputs, input_params, weights, out);
}

// round 6
// speedup vs baseline: 1.6541x; 1.1933x over previous
#include <cuda_runtime.h>

// QuantumConvolution: B=32, Cin=8, Cout=16, H=W=32, K=3, NQ=3, DRC=3, IT=30.
// R6: layer-0 collapsed to a Kronecker product of fused (Rot*RY)|0> columns
//     (72 FMAs vs 172), launch_bounds(256,4) -> 64 regs -> 4 blocks/SM.
//     Scalar FMA path (f32x2 is half-rate), cin-per-lane + shuffle reduce.

#define BB    32
#define CIN   8
#define COUT  16
#define HW    32
#define ITDIM 30
#define NPOS  (ITDIM * ITDIM)   // 900
#define NTHREADS 256
#define CH_STRIDE 1060          // per-channel smem floats: cin lanes on distinct banks

__global__ __launch_bounds__(NTHREADS, 4)
void qconv_kernel(const float* __restrict__ inputs,        // [32][8][32][32]
                  const float* __restrict__ input_params,  // [16][8][3][3]
                  const float* __restrict__ weights,       // [16][8][3][3][3]
                  float* __restrict__ out)                 // [32][16][30][30]
{
    __shared__ float  s_in[CIN * CH_STRIDE];
    __shared__ float  s_pm[CIN][9];       // 0.5 * input_params
    __shared__ float4 s_gc[CIN][9];       // Rot row0: (u00r, u00i, u01r, u01i)

    const int cout = blockIdx.x;
    const int b    = blockIdx.y;
    const int tid  = threadIdx.x;
    const int cin  = tid & 7;
    const int grp  = tid >> 3;            // 32 position groups

    // ---- Load input patch (float4, coalesced) into padded smem ----
    const float4* inb4 = (const float4*)(inputs + (size_t)b * (CIN * HW * HW));
    #pragma unroll
    for (int k = 0; k < 8; k++) {
        int idx = k * NTHREADS + tid;      // 2048 float4 total
        int c   = idx >> 8;
        int rem = idx & 255;
        int row = rem >> 3;
        int col = (rem & 7) * 4;
        float4 v = inb4[idx];
        float* dst = &s_in[c * CH_STRIDE + row * 33 + col];
        dst[0] = v.x; dst[1] = v.y; dst[2] = v.z; dst[3] = v.w;
    }

    // ---- Precompute per-(cin,gate): half params + Rot row-0 ----
    if (tid < CIN * 9) {
        int pc = tid / 9;
        int g  = tid % 9;
        s_pm[pc][g] = 0.5f * input_params[(cout * CIN + pc) * 9 + g];

        const float* w = weights + (((size_t)cout * CIN + pc) * 9 + g) * 3;
        float phi = w[0], th = w[1], om = w[2];
        float st, ct;  sincosf(0.5f * th, &st, &ct);
        float sa, ca;  sincosf(0.5f * (phi + om), &sa, &ca);
        float sb, cb;  sincosf(0.5f * (phi - om), &sb, &cb);
        // u00 = ( ca*ct, -sa*ct),  u01 = (-cb*st, -sb*st)
        s_gc[pc][g] = make_float4(ca * ct, -sa * ct, -cb * st, -sb * st);
    }
    __syncthreads();

    const float*  chan = &s_in[cin * CH_STRIDE];
    const float*  pmc  = s_pm[cin];
    const float4* gcc  = s_gc[cin];

    // Apply SU(2) gate V = [[a, -t],[conj(t), conj(a)]] on qubit pairs with stride ST
    #define APPLY(AR, AI, TR, TI, ST)                                           \
    {                                                                           \
        _Pragma("unroll")                                                       \
        for (int a0 = 0; a0 < 8; a0++) {                                        \
            if ((a0 & (ST)) == 0) {                                             \
                int p = a0 | (ST);                                              \
                float x0r = sr[a0], x0i = si[a0];                               \
                float x1r = sr[p],  x1i = si[p];                                \
                sr[a0] = (AR) * x0r - (AI) * x0i - (TR) * x1r + (TI) * x1i;     \
                si[a0] = (AR) * x0i + (AI) * x0r - (TR) * x1i - (TI) * x1r;     \
                sr[p]  = (TR) * x0r + (TI) * x0i + (AR) * x1r + (AI) * x1i;     \
                si[p]  = (TR) * x0i - (TI) * x0r + (AR) * x1i - (AI) * x1r;     \
            }                                                                   \
        }                                                                       \
    }

    // Fused (Rot * RY(theta)) gate: a = u00*c + u01*s, t = u00*s - u01*c
    #define FUSED_GATE(G, ROW, COL, ST)                                         \
    {                                                                           \
        float sn, cs;                                                           \
        __sincosf(win[(ROW) * 33 + (COL)] * pmc[(G)], &sn, &cs);                \
        float4 u = gcc[(G)];                                                    \
        float ar = u.x * cs + u.z * sn;                                         \
        float ai = u.y * cs + u.w * sn;                                         \
        float tr = u.x * sn - u.z * cs;                                         \
        float ti = u.y * sn - u.w * cs;                                         \
        APPLY(ar, ai, tr, ti, ST)                                               \
    }

    #define CNOT_RING()                                                             \
    {                                                                               \
        float t;                                                                    \
        t = sr[4]; sr[4] = sr[6]; sr[6] = t;  t = si[4]; si[4] = si[6]; si[6] = t;  \
        t = sr[5]; sr[5] = sr[7]; sr[7] = t;  t = si[5]; si[5] = si[7]; si[7] = t;  \
        t = sr[2]; sr[2] = sr[3]; sr[3] = t;  t = si[2]; si[2] = si[3]; si[3] = t;  \
        t = sr[6]; sr[6] = sr[7]; sr[7] = t;  t = si[6]; si[6] = si[7]; si[7] = t;  \
        t = sr[1]; sr[1] = sr[5]; sr[5] = t;  t = si[1]; si[1] = si[5]; si[5] = t;  \
        t = sr[3]; sr[3] = sr[7]; sr[7] = t;  t = si[3]; si[3] = si[7]; si[7] = t;  \
    }

    #pragma unroll 1
    for (int pos = grp; pos < NPOS; pos += 32) {
        const int i = pos / ITDIM;
        const int j = pos % ITDIM;
        const float* win = chan + i * 33 + j;

        float sr[8], si[8];

        // ======== Layer 0: full collapse ========
        // All 6 layer-0 gates hit |000> before any entangler, so the state is
        // the Kronecker product of fused-gate first columns (a_q, conj(t_q)).
        {
            float sn, cs;
            // qubit 0 column
            __sincosf(win[0] * pmc[0], &sn, &cs);
            float4 u = gcc[0];
            float a0r = u.x * cs + u.z * sn,  a0i = u.y * cs + u.w * sn;
            float b0r = u.x * sn - u.z * cs,  b0i = u.w * cs - u.y * sn;  // conj(t0)
            // qubit 1 column
            __sincosf(win[1] * pmc[1], &sn, &cs);
            u = gcc[1];
            float a1r = u.x * cs + u.z * sn,  a1i = u.y * cs + u.w * sn;
            float b1r = u.x * sn - u.z * cs,  b1i = u.w * cs - u.y * sn;
            // qubit 2 column
            __sincosf(win[2] * pmc[2], &sn, &cs);
            u = gcc[2];
            float a2r = u.x * cs + u.z * sn,  a2i = u.y * cs + u.w * sn;
            float b2r = u.x * sn - u.z * cs,  b2i = u.w * cs - u.y * sn;

            // m = (a1,b1) (x) (a2,b2)   [4 complex muls]
            float m0r = a1r * a2r - a1i * a2i,  m0i = a1r * a2i + a1i * a2r;
            float m1r = a1r * b2r - a1i * b2i,  m1i = a1r * b2i + a1i * b2r;
            float m2r = b1r * a2r - b1i * a2i,  m2i = b1r * a2i + b1i * a2r;
            float m3r = b1r * b2r - b1i * b2i,  m3i = b1r * b2i + b1i * b2r;

            // s = (a0,b0) (x) m   [8 complex muls]
            sr[0] = a0r * m0r - a0i * m0i;  si[0] = a0r * m0i + a0i * m0r;
            sr[1] = a0r * m1r - a0i * m1i;  si[1] = a0r * m1i + a0i * m1r;
            sr[2] = a0r * m2r - a0i * m2i;  si[2] = a0r * m2i + a0i * m2r;
            sr[3] = a0r * m3r - a0i * m3i;  si[3] = a0r * m3i + a0i * m3r;
            sr[4] = b0r * m0r - b0i * m0i;  si[4] = b0r * m0i + b0i * m0r;
            sr[5] = b0r * m1r - b0i * m1i;  si[5] = b0r * m1i + b0i * m1r;
            sr[6] = b0r * m2r - b0i * m2i;  si[6] = b0r * m2i + b0i * m2r;
            sr[7] = b0r * m3r - b0i * m3i;  si[7] = b0r * m3i + b0i * m3r;
        }
        CNOT_RING()

        // ======== Layer 1 (RY fused into Rot) ========
        FUSED_GATE(3, 1, 0, 4)
        FUSED_GATE(4, 1, 1, 2)
        FUSED_GATE(5, 1, 2, 1)
        CNOT_RING()

        // ======== Layer 2 ========
        FUSED_GATE(6, 2, 0, 4)
        FUSED_GATE(7, 2, 1, 2)
        FUSED_GATE(8, 2, 2, 1)
        CNOT_RING()

        // <Z wire2>: + even amp index, - odd
        float acc = 0.f;
        #pragma unroll
        for (int a0 = 0; a0 < 8; a0++) {
            float p2 = sr[a0] * sr[a0] + si[a0] * si[a0];
            acc += (a0 & 1) ? -p2 : p2;
        }

        // reduce over the 8 cin lanes
        acc += __shfl_xor_sync(0xFFFFFFFFu, acc, 1);
        acc += __shfl_xor_sync(0xFFFFFFFFu, acc, 2);
        acc += __shfl_xor_sync(0xFFFFFFFFu, acc, 4);
        if (cin == 0)
            out[((size_t)b * COUT + cout) * NPOS + pos] = acc;
    }

    #undef APPLY
    #undef FUSED_GATE
    #undef CNOT_RING
}

extern "C" void kernel_launch(void* const* d_in, const int* in_sizes, int n_in,
                              void* d_out, int out_size)
{
    const float* inputs       = (const float*)d_in[0];
    const float* input_params = (const float*)d_in[1];
    const float* weights      = (const float*)d_in[2];
    float* out = (float*)d_out;

    dim3 grid(COUT, BB);   // (cout, b)
    qconv_kernel<<<grid, NTHREADS>>>(inputs, input_params, weights, out);
}

// round 8
// speedup vs baseline: 1.6814x; 1.0165x over previous
#include <cuda_runtime.h>

// QuantumConvolution: B=32, Cin=8, Cout=16, H=W=32, K=3, NQ=3, DRC=3, IT=30.
// R8: R7 with the measurement-fold cross-term factor fixed (2*Re(p x0* x1):
//     pr,pi built with -4 not -2). 64-thread blocks (8 pos-groups x 8 cin),
//     launch_bounds(64,16) -> 32 warps/SM, 4 row-bands -> 2048 blocks (~1% imbalance).
//     Layer-0 Kronecker collapse, SU(2) fused Rot*RY, M = V2' Z V2 measurement fold.

#define BB    32
#define CIN   8
#define COUT  16
#define HW    32
#define ITDIM 30
#define NBAND 4
#define BROWS 8                 // output rows per band (last band: 6)
#define NTHREADS 64
#define ROWS_MAX 10             // input rows held (BROWS + 2)
#define ROW_STRIDE 33
#define CH_STRIDE (ROWS_MAX * ROW_STRIDE)   // 330 floats

__global__ __launch_bounds__(NTHREADS, 16)
void qconv_kernel(const float* __restrict__ inputs,        // [32][8][32][32]
                  const float* __restrict__ input_params,  // [16][8][3][3]
                  const float* __restrict__ weights,       // [16][8][3][3][3]
                  float* __restrict__ out)                 // [32][16][30][30]
{
    __shared__ float  s_in[CIN * CH_STRIDE];
    __shared__ float  s_pm[CIN][9];       // 0.5 * input_params
    __shared__ float4 s_gc[CIN][9];       // Rot row0: (u00r, u00i, u01r, u01i)

    const int cout = blockIdx.x;
    const int b    = blockIdx.y;
    const int z    = blockIdx.z;          // row band
    const int tid  = threadIdx.x;
    const int cin  = tid & 7;
    const int grp  = tid >> 3;            // 8 position groups

    const int row0  = z * BROWS;
    const int nrows = (z < 3) ? BROWS : (ITDIM - 3 * BROWS);   // 8,8,8,6
    const int nin8  = (nrows + 2) * 8;

    // ---- Load band patch (float4, coalesced) into padded smem ----
    const float4* inb4 = (const float4*)inputs + (size_t)b * (CIN * HW * HW / 4);
    #pragma unroll 1
    for (int c = 0; c < CIN; c++) {
        for (int t4 = tid; t4 < nin8; t4 += NTHREADS) {
            int r    = t4 >> 3;
            int col4 = t4 & 7;
            float4 v = inb4[(c * HW + row0 + r) * 8 + col4];
            float* dst = &s_in[c * CH_STRIDE + r * ROW_STRIDE + col4 * 4];
            dst[0] = v.x; dst[1] = v.y; dst[2] = v.z; dst[3] = v.w;
        }
    }

    // ---- Precompute per-(cin,gate): half params + Rot row-0 ----
    for (int e = tid; e < CIN * 9; e += NTHREADS) {
        int pc = e / 9;
        int g  = e % 9;
        s_pm[pc][g] = 0.5f * input_params[(cout * CIN + pc) * 9 + g];

        const float* w = weights + (((size_t)cout * CIN + pc) * 9 + g) * 3;
        float phi = w[0], th = w[1], om = w[2];
        float st, ct;  sincosf(0.5f * th, &st, &ct);
        float sa, ca;  sincosf(0.5f * (phi + om), &sa, &ca);
        float sb, cb;  sincosf(0.5f * (phi - om), &sb, &cb);
        // u00 = ( ca*ct, -sa*ct),  u01 = (-cb*st, -sb*st)
        s_gc[pc][g] = make_float4(ca * ct, -sa * ct, -cb * st, -sb * st);
    }
    __syncthreads();

    const float*  chan = &s_in[cin * CH_STRIDE];
    const float*  pmc  = s_pm[cin];
    const float4* gcc  = s_gc[cin];

    // Apply SU(2) gate V = [[a, -t],[conj(t), conj(a)]] on pairs with stride ST
    #define APPLY(AR, AI, TR, TI, ST)                                           \
    {                                                                           \
        _Pragma("unroll")                                                       \
        for (int a0 = 0; a0 < 8; a0++) {                                        \
            if ((a0 & (ST)) == 0) {                                             \
                int p = a0 | (ST);                                              \
                float x0r = sr[a0], x0i = si[a0];                               \
                float x1r = sr[p],  x1i = si[p];                                \
                sr[a0] = (AR) * x0r - (AI) * x0i - (TR) * x1r + (TI) * x1i;     \
                si[a0] = (AR) * x0i + (AI) * x0r - (TR) * x1i - (TI) * x1r;     \
                sr[p]  = (TR) * x0r + (TI) * x0i + (AR) * x1r + (AI) * x1i;     \
                si[p]  = (TR) * x0i - (TI) * x0r + (AR) * x1i - (AI) * x1r;     \
            }                                                                   \
        }                                                                       \
    }

    // Fused (Rot * RY(theta)) gate: a = u00*c + u01*s, t = u00*s - u01*c
    #define FUSED_GATE(G, ROW, COL, ST)                                         \
    {                                                                           \
        float sn, cs;                                                           \
        __sincosf(win[(ROW) * ROW_STRIDE + (COL)] * pmc[(G)], &sn, &cs);        \
        float4 u = gcc[(G)];                                                    \
        float ar = u.x * cs + u.z * sn;                                         \
        float ai = u.y * cs + u.w * sn;                                         \
        float tr = u.x * sn - u.z * cs;                                         \
        float ti = u.y * sn - u.w * cs;                                         \
        APPLY(ar, ai, tr, ti, ST)                                               \
    }

    #define CNOT_RING()                                                             \
    {                                                                               \
        float t;                                                                    \
        t = sr[4]; sr[4] = sr[6]; sr[6] = t;  t = si[4]; si[4] = si[6]; si[6] = t;  \
        t = sr[5]; sr[5] = sr[7]; sr[7] = t;  t = si[5]; si[5] = si[7]; si[7] = t;  \
        t = sr[2]; sr[2] = sr[3]; sr[3] = t;  t = si[2]; si[2] = si[3]; si[3] = t;  \
        t = sr[6]; sr[6] = sr[7]; sr[7] = t;  t = si[6]; si[6] = si[7]; si[7] = t;  \
        t = sr[1]; sr[1] = sr[5]; sr[5] = t;  t = si[1]; si[1] = si[5]; si[5] = t;  \
        t = sr[3]; sr[3] = sr[7]; sr[7] = t;  t = si[3]; si[3] = si[7]; si[7] = t;  \
    }

    const int npos = nrows * ITDIM;

    #pragma unroll 1
    for (int k = grp; k < npos; k += 8) {
        const int il = k / ITDIM;
        const int j  = k % ITDIM;
        const float* win = chan + il * ROW_STRIDE + j;

        float sr[8], si[8];

        // ======== Layer 0: Kronecker product of fused (Rot*RY)|0> columns ========
        {
            float sn, cs;
            __sincosf(win[0] * pmc[0], &sn, &cs);
            float4 u = gcc[0];
            float a0r = u.x * cs + u.z * sn,  a0i = u.y * cs + u.w * sn;
            float b0r = u.x * sn - u.z * cs,  b0i = u.w * cs - u.y * sn;  // conj(t0)
            __sincosf(win[1] * pmc[1], &sn, &cs);
            u = gcc[1];
            float a1r = u.x * cs + u.z * sn,  a1i = u.y * cs + u.w * sn;
            float b1r = u.x * sn - u.z * cs,  b1i = u.w * cs - u.y * sn;
            __sincosf(win[2] * pmc[2], &sn, &cs);
            u = gcc[2];
            float a2r = u.x * cs + u.z * sn,  a2i = u.y * cs + u.w * sn;
            float b2r = u.x * sn - u.z * cs,  b2i = u.w * cs - u.y * sn;

            float m0r = a1r * a2r - a1i * a2i,  m0i = a1r * a2i + a1i * a2r;
            float m1r = a1r * b2r - a1i * b2i,  m1i = a1r * b2i + a1i * b2r;
            float m2r = b1r * a2r - b1i * a2i,  m2i = b1r * a2i + b1i * a2r;
            float m3r = b1r * b2r - b1i * b2i,  m3i = b1r * b2i + b1i * b2r;

            sr[0] = a0r * m0r - a0i * m0i;  si[0] = a0r * m0i + a0i * m0r;
            sr[1] = a0r * m1r - a0i * m1i;  si[1] = a0r * m1i + a0i * m1r;
            sr[2] = a0r * m2r - a0i * m2i;  si[2] = a0r * m2i + a0i * m2r;
            sr[3] = a0r * m3r - a0i * m3i;  si[3] = a0r * m3i + a0i * m3r;
            sr[4] = b0r * m0r - b0i * m0i;  si[4] = b0r * m0i + b0i * m0r;
            sr[5] = b0r * m1r - b0i * m1i;  si[5] = b0r * m1i + b0i * m1r;
            sr[6] = b0r * m2r - b0i * m2i;  si[6] = b0r * m2i + b0i * m2r;
            sr[7] = b0r * m3r - b0i * m3i;  si[7] = b0r * m3i + b0i * m3r;
        }
        CNOT_RING()

        // ======== Layer 1 ========
        FUSED_GATE(3, 1, 0, 4)
        FUSED_GATE(4, 1, 1, 2)
        FUSED_GATE(5, 1, 2, 1)
        CNOT_RING()

        // ======== Layer 2: wires 0,1 applied; wire-2 gate + ring + <Z2> folded:
        //          Ring' Z2 Ring = Z0 Z1 Z2 ->  Z0 (x) Z1 (x) (V2' Z V2) ========
        FUSED_GATE(6, 2, 0, 4)
        FUSED_GATE(7, 2, 1, 2)

        float acc;
        {
            float sn, cs;
            __sincosf(win[2 * ROW_STRIDE + 2] * pmc[8], &sn, &cs);
            float4 u = gcc[8];
            float ar = u.x * cs + u.z * sn;
            float ai = u.y * cs + u.w * sn;
            float tr = u.x * sn - u.z * cs;
            float ti = u.y * sn - u.w * cs;
            // M = [[m, p],[conj(p), -m]], m = |a|^2-|t|^2, p = -2*conj(a)*t.
            // <x|M|x> = m(|x0|^2-|x1|^2) + 2*Re(p * conj(x0) * x1)
            // Fold the extra 2 into the constants: use 2p.
            float m  = ar * ar + ai * ai - tr * tr - ti * ti;
            float pr = -4.0f * (ar * tr + ai * ti);
            float pi = -4.0f * (ar * ti - ai * tr);

            #define PAIR_E(K)                                                   \
                (m  * (sr[2*(K)] * sr[2*(K)] + si[2*(K)] * si[2*(K)]            \
                     - sr[2*(K)+1] * sr[2*(K)+1] - si[2*(K)+1] * si[2*(K)+1])   \
               + pr * (sr[2*(K)] * sr[2*(K)+1] + si[2*(K)] * si[2*(K)+1])       \
               - pi * (sr[2*(K)] * si[2*(K)+1] - si[2*(K)] * sr[2*(K)+1]))
            acc = PAIR_E(0) - PAIR_E(1) - PAIR_E(2) + PAIR_E(3);
            #undef PAIR_E
        }

        // reduce over the 8 cin lanes
        acc += __shfl_xor_sync(0xFFFFFFFFu, acc, 1);
        acc += __shfl_xor_sync(0xFFFFFFFFu, acc, 2);
        acc += __shfl_xor_sync(0xFFFFFFFFu, acc, 4);
        if (cin == 0)
            out[((size_t)b * COUT + cout) * (ITDIM * ITDIM) + (row0 + il) * ITDIM + j] = acc;
    }

    #undef APPLY
    #undef FUSED_GATE
    #undef CNOT_RING
}

extern "C" void kernel_launch(void* const* d_in, const int* in_sizes, int n_in,
                              void* d_out, int out_size)
{
    const float* inputs       = (const float*)d_in[0];
    const float* input_params = (const float*)d_in[1];
    const float* weights      = (const float*)d_in[2];
    float* out = (float*)d_out;

    dim3 grid(COUT, BB, NBAND);   // (cout, b, row band)
    qconv_kernel<<<grid, NTHREADS>>>(inputs, input_params, weights, out);
}

// round 9
// speedup vs baseline: 1.6826x; 1.0007x over previous
#include <cuda_runtime.h>

// QuantumConvolution: B=32, Cin=8, Cout=16, H=W=32, K=3, NQ=3, DRC=3, IT=30.
// R9: R8 + (a) gate constants precomputed ONCE in a separate kernel into
//     __device__ globals (removes 2048x redundant heavy sincosf preamble),
//     (b) launch_bounds(64,12) -> ~84 regs -> no spills (R8's 64-reg cap spilled).
//     64-thread blocks (8 pos-groups x 8 cin), 4 row-bands, measurement fold.

#define BB    32
#define CIN   8
#define COUT  16
#define HW    32
#define ITDIM 30
#define NBAND 4
#define BROWS 8
#define NTHREADS 64
#define ROWS_MAX 10
#define ROW_STRIDE 33
#define CH_STRIDE (ROWS_MAX * ROW_STRIDE)
#define NGATE (COUT * CIN * 9)   // 1152

__device__ float4 g_gc[NGATE];   // Rot row0: (u00r, u00i, u01r, u01i)
__device__ float  g_pm[NGATE];   // 0.5 * input_params

__global__ void precompute_kernel(const float* __restrict__ input_params,
                                  const float* __restrict__ weights)
{
    int e = blockIdx.x * blockDim.x + threadIdx.x;
    if (e >= NGATE) return;
    g_pm[e] = 0.5f * input_params[e];
    const float* w = weights + (size_t)e * 3;
    float phi = w[0], th = w[1], om = w[2];
    float st, ct;  sincosf(0.5f * th, &st, &ct);
    float sa, ca;  sincosf(0.5f * (phi + om), &sa, &ca);
    float sb, cb;  sincosf(0.5f * (phi - om), &sb, &cb);
    // u00 = ( ca*ct, -sa*ct),  u01 = (-cb*st, -sb*st)
    g_gc[e] = make_float4(ca * ct, -sa * ct, -cb * st, -sb * st);
}

__global__ __launch_bounds__(NTHREADS, 12)
void qconv_kernel(const float* __restrict__ inputs,   // [32][8][32][32]
                  float* __restrict__ out)            // [32][16][30][30]
{
    __shared__ float  s_in[CIN * CH_STRIDE];
    __shared__ float  s_pm[CIN * 9];
    __shared__ float4 s_gc[CIN * 9];

    const int cout = blockIdx.x;
    const int b    = blockIdx.y;
    const int z    = blockIdx.z;
    const int tid  = threadIdx.x;
    const int cin  = tid & 7;
    const int grp  = tid >> 3;

    const int row0  = z * BROWS;
    const int nrows = (z < 3) ? BROWS : (ITDIM - 3 * BROWS);   // 8,8,8,6
    const int nin8  = (nrows + 2) * 8;

    // ---- Load band patch (float4, coalesced) into padded smem ----
    const float4* inb4 = (const float4*)inputs + (size_t)b * (CIN * HW * HW / 4);
    #pragma unroll 1
    for (int c = 0; c < CIN; c++) {
        for (int t4 = tid; t4 < nin8; t4 += NTHREADS) {
            int r    = t4 >> 3;
            int col4 = t4 & 7;
            float4 v = inb4[(c * HW + row0 + r) * 8 + col4];
            float* dst = &s_in[c * CH_STRIDE + r * ROW_STRIDE + col4 * 4];
            dst[0] = v.x; dst[1] = v.y; dst[2] = v.z; dst[3] = v.w;
        }
    }

    // ---- Copy precomputed gate constants (L2-resident) ----
    {
        const int base = cout * CIN * 9;
        for (int e = tid; e < CIN * 9; e += NTHREADS) {
            s_gc[e] = g_gc[base + e];
            s_pm[e] = g_pm[base + e];
        }
    }
    __syncthreads();

    const float*  chan = &s_in[cin * CH_STRIDE];
    const float*  pmc  = &s_pm[cin * 9];
    const float4* gcc  = &s_gc[cin * 9];

    // Apply SU(2) gate V = [[a, -t],[conj(t), conj(a)]] on pairs with stride ST
    #define APPLY(AR, AI, TR, TI, ST)                                           \
    {                                                                           \
        _Pragma("unroll")                                                       \
        for (int a0 = 0; a0 < 8; a0++) {                                        \
            if ((a0 & (ST)) == 0) {                                             \
                int p = a0 | (ST);                                              \
                float x0r = sr[a0], x0i = si[a0];                               \
                float x1r = sr[p],  x1i = si[p];                                \
                sr[a0] = (AR) * x0r - (AI) * x0i - (TR) * x1r + (TI) * x1i;     \
                si[a0] = (AR) * x0i + (AI) * x0r - (TR) * x1i - (TI) * x1r;     \
                sr[p]  = (TR) * x0r + (TI) * x0i + (AR) * x1r + (AI) * x1i;     \
                si[p]  = (TR) * x0i - (TI) * x0r + (AR) * x1i - (AI) * x1r;     \
            }                                                                   \
        }                                                                       \
    }

    // Fused (Rot * RY(theta)) gate: a = u00*c + u01*s, t = u00*s - u01*c
    #define FUSED_GATE(G, ROW, COL, ST)                                         \
    {                                                                           \
        float sn, cs;                                                           \
        __sincosf(win[(ROW) * ROW_STRIDE + (COL)] * pmc[(G)], &sn, &cs);        \
        float4 u = gcc[(G)];                                                    \
        float ar = u.x * cs + u.z * sn;                                         \
        float ai = u.y * cs + u.w * sn;                                         \
        float tr = u.x * sn - u.z * cs;                                         \
        float ti = u.y * sn - u.w * cs;                                         \
        APPLY(ar, ai, tr, ti, ST)                                               \
    }

    #define CNOT_RING()                                                             \
    {                                                                               \
        float t;                                                                    \
        t = sr[4]; sr[4] = sr[6]; sr[6] = t;  t = si[4]; si[4] = si[6]; si[6] = t;  \
        t = sr[5]; sr[5] = sr[7]; sr[7] = t;  t = si[5]; si[5] = si[7]; si[7] = t;  \
        t = sr[2]; sr[2] = sr[3]; sr[3] = t;  t = si[2]; si[2] = si[3]; si[3] = t;  \
        t = sr[6]; sr[6] = sr[7]; sr[7] = t;  t = si[6]; si[6] = si[7]; si[7] = t;  \
        t = sr[1]; sr[1] = sr[5]; sr[5] = t;  t = si[1]; si[1] = si[5]; si[5] = t;  \
        t = sr[3]; sr[3] = sr[7]; sr[7] = t;  t = si[3]; si[3] = si[7]; si[7] = t;  \
    }

    const int npos = nrows * ITDIM;

    #pragma unroll 1
    for (int k = grp; k < npos; k += 8) {
        const int il = k / ITDIM;
        const int j  = k % ITDIM;
        const float* win = chan + il * ROW_STRIDE + j;

        float sr[8], si[8];

        // ======== Layer 0: Kronecker product of fused (Rot*RY)|0> columns ========
        {
            float sn, cs;
            __sincosf(win[0] * pmc[0], &sn, &cs);
            float4 u = gcc[0];
            float a0r = u.x * cs + u.z * sn,  a0i = u.y * cs + u.w * sn;
            float b0r = u.x * sn - u.z * cs,  b0i = u.w * cs - u.y * sn;  // conj(t0)
            __sincosf(win[1] * pmc[1], &sn, &cs);
            u = gcc[1];
            float a1r = u.x * cs + u.z * sn,  a1i = u.y * cs + u.w * sn;
            float b1r = u.x * sn - u.z * cs,  b1i = u.w * cs - u.y * sn;
            __sincosf(win[2] * pmc[2], &sn, &cs);
            u = gcc[2];
            float a2r = u.x * cs + u.z * sn,  a2i = u.y * cs + u.w * sn;
            float b2r = u.x * sn - u.z * cs,  b2i = u.w * cs - u.y * sn;

            float m0r = a1r * a2r - a1i * a2i,  m0i = a1r * a2i + a1i * a2r;
            float m1r = a1r * b2r - a1i * b2i,  m1i = a1r * b2i + a1i * b2r;
            float m2r = b1r * a2r - b1i * a2i,  m2i = b1r * a2i + b1i * a2r;
            float m3r = b1r * b2r - b1i * b2i,  m3i = b1r * b2i + b1i * b2r;

            sr[0] = a0r * m0r - a0i * m0i;  si[0] = a0r * m0i + a0i * m0r;
            sr[1] = a0r * m1r - a0i * m1i;  si[1] = a0r * m1i + a0i * m1r;
            sr[2] = a0r * m2r - a0i * m2i;  si[2] = a0r * m2i + a0i * m2r;
            sr[3] = a0r * m3r - a0i * m3i;  si[3] = a0r * m3i + a0i * m3r;
            sr[4] = b0r * m0r - b0i * m0i;  si[4] = b0r * m0i + b0i * m0r;
            sr[5] = b0r * m1r - b0i * m1i;  si[5] = b0r * m1i + b0i * m1r;
            sr[6] = b0r * m2r - b0i * m2i;  si[6] = b0r * m2i + b0i * m2r;
            sr[7] = b0r * m3r - b0i * m3i;  si[7] = b0r * m3i + b0i * m3r;
        }
        CNOT_RING()

        // ======== Layer 1 ========
        FUSED_GATE(3, 1, 0, 4)
        FUSED_GATE(4, 1, 1, 2)
        FUSED_GATE(5, 1, 2, 1)
        CNOT_RING()

        // ======== Layer 2: wires 0,1 applied; wire-2 gate + ring + <Z2> folded:
        //          Ring' Z2 Ring = Z0 Z1 Z2 -> Z0 (x) Z1 (x) (V2' Z V2) ========
        FUSED_GATE(6, 2, 0, 4)
        FUSED_GATE(7, 2, 1, 2)

        float acc;
        {
            float sn, cs;
            __sincosf(win[2 * ROW_STRIDE + 2] * pmc[8], &sn, &cs);
            float4 u = gcc[8];
            float ar = u.x * cs + u.z * sn;
            float ai = u.y * cs + u.w * sn;
            float tr = u.x * sn - u.z * cs;
            float ti = u.y * sn - u.w * cs;
            // M = [[m, p],[conj(p), -m]], m = |a|^2-|t|^2, p = -2*conj(a)*t.
            // <x|M|x> = m(|x0|^2-|x1|^2) + 2*Re(p conj(x0) x1) -> fold 2 into p.
            float m  = ar * ar + ai * ai - tr * tr - ti * ti;
            float pr = -4.0f * (ar * tr + ai * ti);
            float pi = -4.0f * (ar * ti - ai * tr);

            #define PAIR_E(K)                                                   \
                (m  * (sr[2*(K)] * sr[2*(K)] + si[2*(K)] * si[2*(K)]            \
                     - sr[2*(K)+1] * sr[2*(K)+1] - si[2*(K)+1] * si[2*(K)+1])   \
               + pr * (sr[2*(K)] * sr[2*(K)+1] + si[2*(K)] * si[2*(K)+1])       \
               - pi * (sr[2*(K)] * si[2*(K)+1] - si[2*(K)] * sr[2*(K)+1]))
            acc = PAIR_E(0) - PAIR_E(1) - PAIR_E(2) + PAIR_E(3);
            #undef PAIR_E
        }

        // reduce over the 8 cin lanes
        acc += __shfl_xor_sync(0xFFFFFFFFu, acc, 1);
        acc += __shfl_xor_sync(0xFFFFFFFFu, acc, 2);
        acc += __shfl_xor_sync(0xFFFFFFFFu, acc, 4);
        if (cin == 0)
            out[((size_t)b * COUT + cout) * (ITDIM * ITDIM) + (row0 + il) * ITDIM + j] = acc;
    }

    #undef APPLY
    #undef FUSED_GATE
    #undef CNOT_RING
}

extern "C" void kernel_launch(void* const* d_in, const int* in_sizes, int n_in,
                              void* d_out, int out_size)
{
    const float* inputs       = (const float*)d_in[0];
    const float* input_params = (const float*)d_in[1];
    const float* weights      = (const float*)d_in[2];
    float* out = (float*)d_out;

    precompute_kernel<<<(NGATE + 127) / 128, 128>>>(input_params, weights);
    dim3 grid(COUT, BB, NBAND);   // (cout, b, row band)
    qconv_kernel<<<grid, NTHREADS>>>(inputs, out);
}